// round 17
// baseline (speedup 1.0000x reference)
#include <cuda_runtime.h>
#include <math.h>

#define BATCH 4
#define SEQ   2048
#define QDIM  1024
#define HEADS 16
#define DHEAD 64
#define MROWS (BATCH*SEQ)          // 8192
#define SCALE 0.125f
#define NKB   (SEQ/64)

// tf32 scratch. Interleave: within each 8-col group, col k' lives at
// slot (k'>>2) + 2*(k'&3)  (mma pair (kq, kq+4) adjacent).
__device__ unsigned hid_tf[MROWS*QDIM];     // [M][K] k-interleaved (A of qkv)
__device__ unsigned wqt_tf[QDIM*QDIM];      // [N][K] transposed + k-interleaved
__device__ unsigned wkt_tf[QDIM*QDIM];
__device__ unsigned wvt_tf[QDIM*QDIM];
__device__ unsigned wot_tf[QDIM*QDIM];
__device__ unsigned g_q[BATCH*HEADS*SEQ*DHEAD];   // [B,H,T,dh] natural (pre-scaled)
__device__ unsigned g_k[BATCH*HEADS*SEQ*DHEAD];   // [B,H,T,dh] dh-interleaved
__device__ unsigned g_v[BATCH*HEADS*SEQ*DHEAD];   // [B,H,dh,T] transposed, t-interleaved
__device__ unsigned g_att[MROWS*QDIM];            // [M][K] k-interleaved (A of proj)

// ---------------------------------------------------------------------------
__device__ __forceinline__ unsigned f2tf(float x) {
    unsigned r;
    asm("cvt.rna.tf32.f32 %0, %1;" : "=r"(r) : "f"(x));
    return r;
}
__device__ __forceinline__ void mma8(float c[4], const unsigned a[4], const unsigned b[2]) {
    asm volatile(
        "mma.sync.aligned.m16n8k8.row.col.f32.tf32.tf32.f32 "
        "{%0,%1,%2,%3}, {%4,%5,%6,%7}, {%8,%9}, {%0,%1,%2,%3};"
        : "+f"(c[0]), "+f"(c[1]), "+f"(c[2]), "+f"(c[3])
        : "r"(a[0]), "r"(a[1]), "r"(a[2]), "r"(a[3]), "r"(b[0]), "r"(b[1]));
}
__device__ __forceinline__ void cp16(void* smem_dst, const void* gsrc) {
    unsigned s = (unsigned)__cvta_generic_to_shared(smem_dst);
    asm volatile("cp.async.cg.shared.global [%0], [%1], 16;" :: "r"(s), "l"(gsrc));
}
#define CP_COMMIT() asm volatile("cp.async.commit_group;")
#define CP_WAIT(N)  asm volatile("cp.async.wait_group %0;" :: "n"(N))

// ---------------------------------------------------------------------------
// One-shot conversions
// ---------------------------------------------------------------------------
#define HID4 (MROWS*QDIM/4)
__global__ __launch_bounds__(256) void cvt_hid_kernel(const float* __restrict__ hidden)
{
    int i = blockIdx.x * blockDim.x + threadIdx.x;
    float4 v = reinterpret_cast<const float4*>(hidden)[i];
    int row = i >> 8, col = (i & 255) * 4;
    int s = col >> 3, bsel = (col >> 2) & 1;
    unsigned* d = &hid_tf[(size_t)row * QDIM + s * 8 + bsel];
    d[0] = f2tf(v.x); d[2] = f2tf(v.y); d[4] = f2tf(v.z); d[6] = f2tf(v.w);
}

// W[k][n] f32 -> Wt[n][k-interleaved] tf32. Wq pre-scaled by SCALE.
__global__ void wt_kernel(const float* __restrict__ Wq, const float* __restrict__ Wk,
                          const float* __restrict__ Wv, const float* __restrict__ Wo)
{
    const int w = blockIdx.z;
    const float* src = (w == 0) ? Wq : (w == 1) ? Wk : (w == 2) ? Wv : Wo;
    unsigned*   dst  = (w == 0) ? wqt_tf : (w == 1) ? wkt_tf : (w == 2) ? wvt_tf : wot_tf;

    __shared__ unsigned t[32][33];
    const int tx = threadIdx.x, ty = threadIdx.y;
    const int x  = blockIdx.x * 32 + tx;    // n
    const int y0 = blockIdx.y * 32;         // k base
    #pragma unroll
    for (int j = 0; j < 4; j++) {
        float v = src[(size_t)(y0 + ty + j * 8) * QDIM + x];
        if (w == 0) v *= SCALE;
        t[ty + j * 8][tx] = f2tf(v);
    }
    __syncthreads();
    const int kin = ((tx & 7) >> 2) + 2 * (tx & 3);
    const int kcol = y0 + (tx >> 3) * 8 + kin;
    #pragma unroll
    for (int j = 0; j < 4; j++) {
        int n = blockIdx.x * 32 + ty + j * 8;
        dst[(size_t)n * QDIM + kcol] = t[tx][ty + j * 8];
    }
}

// ---------------------------------------------------------------------------
// Multistage GEMM (R11-proven): CTA 128x128, GBK=32, 3-stage cp.async.
// ---------------------------------------------------------------------------
#define GBK 32
#define NT  (QDIM/GBK)
#define STR 40
#define TILEW (128*STR)
#define STAGEW (2*TILEW)
#define NSTAGE 3
#define GSMEM (NSTAGE*STAGEW*4)

__device__ __forceinline__ void stage_issue(
    unsigned* As, unsigned* Bs,
    const unsigned* __restrict__ A, const unsigned* __restrict__ Bt,
    int bm, int bn, int k0, int tid)
{
    #pragma unroll
    for (int l = 0; l < 4; l++) {
        int lin = tid + l * 256;
        int row = lin >> 3, ch = lin & 7;
        cp16(&As[row * STR + ch * 4], &A[(size_t)(bm + row) * QDIM + k0 + ch * 4]);
        cp16(&Bs[row * STR + ch * 4], &Bt[(size_t)(bn + row) * QDIM + k0 + ch * 4]);
    }
}

__device__ __forceinline__ void stage_compute(
    const unsigned* As, const unsigned* Bs,
    int wm, int wn, int r, int kq, float acc[4][4][4])
{
    #pragma unroll
    for (int s = 0; s < 4; s++) {
        unsigned af[4][4];
        #pragma unroll
        for (int mi = 0; mi < 4; mi++) {
            int row = wm * 64 + mi * 16 + r;
            uint2 lo = *reinterpret_cast<const uint2*>(&As[row * STR + s * 8 + 2 * kq]);
            uint2 hi = *reinterpret_cast<const uint2*>(&As[(row + 8) * STR + s * 8 + 2 * kq]);
            af[mi][0] = lo.x; af[mi][2] = lo.y; af[mi][1] = hi.x; af[mi][3] = hi.y;
        }
        #pragma unroll
        for (int ni = 0; ni < 4; ni++) {
            int c = wn * 32 + ni * 8 + r;
            uint2 bb = *reinterpret_cast<const uint2*>(&Bs[c * STR + s * 8 + 2 * kq]);
            unsigned bf[2] = {bb.x, bb.y};
            #pragma unroll
            for (int mi = 0; mi < 4; mi++) mma8(acc[mi][ni], af[mi], bf);
        }
    }
}

__device__ __forceinline__ void gemm_mainloop(
    const unsigned* __restrict__ A, const unsigned* __restrict__ Bt,
    int bm, int bn, unsigned* sm, int tid, int wm, int wn, int r, int kq,
    float acc[4][4][4])
{
    stage_issue(sm, sm + TILEW, A, Bt, bm, bn, 0, tid);
    CP_COMMIT();
    stage_issue(sm + STAGEW, sm + STAGEW + TILEW, A, Bt, bm, bn, GBK, tid);
    CP_COMMIT();

    for (int it = 0; it < NT; it++) {
        if (it + 1 < NT) { CP_WAIT(1); } else { CP_WAIT(0); }
        __syncthreads();
        if (it + 2 < NT) {
            unsigned* buf = sm + ((it + 2) % NSTAGE) * STAGEW;
            stage_issue(buf, buf + TILEW, A, Bt, bm, bn, (it + 2) * GBK, tid);
            CP_COMMIT();
        }
        const unsigned* cb = sm + (it % NSTAGE) * STAGEW;
        stage_compute(cb, cb + TILEW, wm, wn, r, kq, acc);
    }
}

// Fused QKV projection. g_q natural; g_k dh-interleaved; g_v transposed [B,H,dh,T].
__global__ __launch_bounds__(256) void qkv_kernel()
{
    const unsigned* Bt = (blockIdx.z == 0) ? wqt_tf : ((blockIdx.z == 1) ? wkt_tf : wvt_tf);
    unsigned* dst      = (blockIdx.z == 0) ? g_q   : ((blockIdx.z == 1) ? g_k   : g_v);

    extern __shared__ unsigned sm[];
    const int tid = threadIdx.x, lane = tid & 31, warp = tid >> 5;
    const int wm = warp >> 2, wn = warp & 3;
    const int r = lane >> 2, kq = lane & 3;
    const int bm = blockIdx.x * 128, bn = blockIdx.y * 128;

    float acc[4][4][4];
    #pragma unroll
    for (int mi = 0; mi < 4; mi++)
        #pragma unroll
        for (int ni = 0; ni < 4; ni++)
            #pragma unroll
            for (int c = 0; c < 4; c++) acc[mi][ni][c] = 0.f;

    gemm_mainloop(hid_tf, Bt, bm, bn, sm, tid, wm, wn, r, kq, acc);

    const int pslot = ((2 * kq) >> 2) + 2 * ((2 * kq) & 3);   // slot of dh col 2kq
    const int slotr = (r >> 2) + 2 * (r & 3);                  // slot of t (r mod 8)
    #pragma unroll
    for (int mi = 0; mi < 4; mi++) {
        #pragma unroll
        for (int ni = 0; ni < 4; ni++) {
            int m0 = bm + wm * 64 + mi * 16 + r;
            int d  = wn * 32 + ni * 8 + 2 * kq;
            int head = (bn + d) >> 6, dd = d & 63;
            int b0 = m0 >> 11, t0 = m0 & 2047;
            unsigned v0 = f2tf(acc[mi][ni][0]), v1 = f2tf(acc[mi][ni][1]);
            unsigned v2 = f2tf(acc[mi][ni][2]), v3 = f2tf(acc[mi][ni][3]);
            if (blockIdx.z == 0) {
                size_t base0 = ((size_t)(b0 * HEADS + head) * SEQ + t0) * DHEAD;
                *reinterpret_cast<uint2*>(&dst[base0 + dd]) = make_uint2(v0, v1);
                *reinterpret_cast<uint2*>(&dst[base0 + 8 * DHEAD + dd]) = make_uint2(v2, v3);
            } else if (blockIdx.z == 1) {
                size_t base0 = ((size_t)(b0 * HEADS + head) * SEQ + t0) * DHEAD;
                size_t g0 = base0 + (dd >> 3) * 8 + pslot;
                dst[g0] = v0; dst[g0 + 2] = v1;
                dst[g0 + 8 * DHEAD] = v2; dst[g0 + 8 * DHEAD + 2] = v3;
            } else {
                // transposed: [B,H,dh,T], t-interleaved within 8-groups
                size_t vb = ((size_t)(b0 * HEADS + head) * DHEAD + dd) * SEQ
                            + (size_t)(t0 & ~7) + slotr;
                dst[vb] = v0; dst[vb + 8] = v2;
                dst[vb + SEQ] = v1; dst[vb + SEQ + 8] = v3;
            }
        }
    }
}

// Output projection: out = g_att @ Wo + bo (f32 out)
__global__ __launch_bounds__(256) void proj_kernel(
    const float* __restrict__ bo, float* __restrict__ C)
{
    extern __shared__ unsigned sm[];
    const int tid = threadIdx.x, lane = tid & 31, warp = tid >> 5;
    const int wm = warp >> 2, wn = warp & 3;
    const int r = lane >> 2, kq = lane & 3;
    const int bm = blockIdx.x * 128, bn = blockIdx.y * 128;

    float acc[4][4][4];
    #pragma unroll
    for (int mi = 0; mi < 4; mi++)
        #pragma unroll
        for (int ni = 0; ni < 4; ni++)
            #pragma unroll
            for (int c = 0; c < 4; c++) acc[mi][ni][c] = 0.f;

    gemm_mainloop(g_att, wot_tf, bm, bn, sm, tid, wm, wn, r, kq, acc);

    #pragma unroll
    for (int mi = 0; mi < 4; mi++) {
        #pragma unroll
        for (int ni = 0; ni < 4; ni++) {
            int m0 = bm + wm * 64 + mi * 16 + r;
            int d  = wn * 32 + ni * 8 + 2 * kq;
            float bx = bo[bn + d], by = bo[bn + d + 1];
            *reinterpret_cast<float2*>(&C[(size_t)m0 * QDIM + bn + d]) =
                make_float2(acc[mi][ni][0] + bx, acc[mi][ni][1] + by);
            *reinterpret_cast<float2*>(&C[(size_t)(m0 + 8) * QDIM + bn + d]) =
                make_float2(acc[mi][ni][2] + bx, acc[mi][ni][3] + by);
        }
    }
}

// ---------------------------------------------------------------------------
// Flash attention v2: CTA 128 q rows, 128 threads = 4 warps, warp 32x64.
// Q frags in registers; P overlays Q-stage smem; K/V fills vectorized from
// pre-interleaved/transposed gmem; V b-frags single LDS.64.
// ---------------------------------------------------------------------------
#define ATW 72
#define ATTN_SMEM ((128*ATW + 64*ATW + 64*ATW) * 4 + 64 * 4)

__global__ __launch_bounds__(128, 2) void attn_kernel(const int* __restrict__ mask)
{
    extern __shared__ unsigned smu[];
    unsigned* Qs = smu;                       // [128][72] staging; overlaid by P
    unsigned* Pw = smu;                       // 4 x [32][72]
    unsigned* Ks = smu + 128 * ATW;           // [64][72] keys x dh-interleaved
    unsigned* Vt = Ks + 64 * ATW;             // [64][72] dh x key-interleaved
    float* mskf  = (float*)(Vt + 64 * ATW);   // [64]

    const int tid = threadIdx.x, lane = tid & 31, warp = tid >> 5;   // warp 0..3
    const int r = lane >> 2, kq = lane & 3;
    const int qb = blockIdx.x, h = blockIdx.y, b = blockIdx.z;
    const size_t bh = (size_t)(b * HEADS + h) * SEQ;
    const size_t vtb = (size_t)(b * HEADS + h) * DHEAD * SEQ;

    // stage Q (natural -> interleaved smem), then hoist frags to registers
    const unsigned* qg = &g_q[(bh + qb * 128) * DHEAD];
    #pragma unroll
    for (int l = 0; l < 16; l++) {
        int lin = tid + l * 128;
        int row = lin >> 4, kg = lin & 15;
        uint4 v = *reinterpret_cast<const uint4*>(&qg[row * DHEAD + kg * 4]);
        unsigned* d = &Qs[row * ATW + (kg >> 1) * 8 + (kg & 1)];
        d[0] = v.x; d[2] = v.y; d[4] = v.z; d[6] = v.w;
    }
    __syncthreads();

    unsigned qf[8][8];
    const int rw = warp * 32 + r;
    #pragma unroll
    for (int s = 0; s < 8; s++) {
        uint2 a0 = *reinterpret_cast<const uint2*>(&Qs[rw * ATW + s * 8 + 2 * kq]);
        uint2 a1 = *reinterpret_cast<const uint2*>(&Qs[(rw + 8) * ATW + s * 8 + 2 * kq]);
        uint2 a2 = *reinterpret_cast<const uint2*>(&Qs[(rw + 16) * ATW + s * 8 + 2 * kq]);
        uint2 a3 = *reinterpret_cast<const uint2*>(&Qs[(rw + 24) * ATW + s * 8 + 2 * kq]);
        qf[s][0] = a0.x; qf[s][1] = a1.x; qf[s][2] = a0.y; qf[s][3] = a1.y;
        qf[s][4] = a2.x; qf[s][5] = a3.x; qf[s][6] = a2.y; qf[s][7] = a3.y;
    }
    __syncthreads();   // Q reads done before P overwrites

    float oacc[2][8][4];
    #pragma unroll
    for (int g = 0; g < 2; g++)
        #pragma unroll
        for (int ni = 0; ni < 8; ni++)
            #pragma unroll
            for (int c = 0; c < 4; c++) oacc[g][ni][c] = 0.f;
    float mst[4] = {-1e30f, -1e30f, -1e30f, -1e30f};
    float lst[4] = {0.f, 0.f, 0.f, 0.f};

    unsigned* Pme = Pw + warp * 32 * ATW;
    const int se0 = ((2 * kq) >> 2) + 2 * ((2 * kq) & 3);

    for (int kb = 0; kb < NKB; kb++) {
        __syncthreads();
        // vectorized K / Vt fills (pre-interleaved gmem)
        const unsigned* kgp = &g_k[(bh + kb * 64) * DHEAD];
        const unsigned* vgp = &g_v[vtb + kb * 64];
        #pragma unroll
        for (int l = 0; l < 8; l++) {
            int lin = tid + l * 128;
            int row = lin >> 4, ch = lin & 15;
            *reinterpret_cast<uint4*>(&Ks[row * ATW + ch * 4]) =
                *reinterpret_cast<const uint4*>(&kgp[row * DHEAD + ch * 4]);
            *reinterpret_cast<uint4*>(&Vt[row * ATW + ch * 4]) =
                *reinterpret_cast<const uint4*>(&vgp[(size_t)row * SEQ + ch * 4]);
        }
        if (tid < 64) mskf[tid] = (mask[b * SEQ + kb * 64 + tid] == 0) ? -1e30f : 0.f;
        __syncthreads();

        // per m-group: S = Q K^T, mask, online softmax, P store, O rescale
        #pragma unroll
        for (int g = 0; g < 2; g++) {
            float sacc[8][4];
            #pragma unroll
            for (int ni = 0; ni < 8; ni++)
                #pragma unroll
                for (int c = 0; c < 4; c++) sacc[ni][c] = 0.f;

            #pragma unroll
            for (int s = 0; s < 8; s++) {
                unsigned af[4] = {qf[s][g*4+0], qf[s][g*4+1], qf[s][g*4+2], qf[s][g*4+3]};
                #pragma unroll
                for (int ni = 0; ni < 8; ni++) {
                    uint2 kf = *reinterpret_cast<const uint2*>(
                        &Ks[(ni * 8 + r) * ATW + s * 8 + 2 * kq]);
                    unsigned bf[2] = {kf.x, kf.y};
                    mma8(sacc[ni], af, bf);
                }
            }

            float rx0 = -1e30f, rx1 = -1e30f;
            #pragma unroll
            for (int ni = 0; ni < 8; ni++) {
                float2 mb = *reinterpret_cast<const float2*>(&mskf[ni * 8 + 2 * kq]);
                sacc[ni][0] += mb.x; sacc[ni][1] += mb.y;
                sacc[ni][2] += mb.x; sacc[ni][3] += mb.y;
                rx0 = fmaxf(rx0, fmaxf(sacc[ni][0], sacc[ni][1]));
                rx1 = fmaxf(rx1, fmaxf(sacc[ni][2], sacc[ni][3]));
            }
            rx0 = fmaxf(rx0, __shfl_xor_sync(0xffffffffu, rx0, 1));
            rx0 = fmaxf(rx0, __shfl_xor_sync(0xffffffffu, rx0, 2));
            rx1 = fmaxf(rx1, __shfl_xor_sync(0xffffffffu, rx1, 1));
            rx1 = fmaxf(rx1, __shfl_xor_sync(0xffffffffu, rx1, 2));

            float mn0 = fmaxf(mst[g*2], rx0), mn1 = fmaxf(mst[g*2+1], rx1);
            float a0 = __expf(mst[g*2] - mn0), a1 = __expf(mst[g*2+1] - mn1);
            float rs0 = 0.f, rs1 = 0.f;
            int pr0 = g * 16 + r;
            #pragma unroll
            for (int ni = 0; ni < 8; ni++) {
                float p00 = __expf(sacc[ni][0] - mn0);
                float p01 = __expf(sacc[ni][1] - mn0);
                float p10 = __expf(sacc[ni][2] - mn1);
                float p11 = __expf(sacc[ni][3] - mn1);
                rs0 += p00 + p01; rs1 += p10 + p11;
                Pme[pr0 * ATW + ni * 8 + se0]           = f2tf(p00);
                Pme[pr0 * ATW + ni * 8 + se0 + 2]       = f2tf(p01);
                Pme[(pr0 + 8) * ATW + ni * 8 + se0]     = f2tf(p10);
                Pme[(pr0 + 8) * ATW + ni * 8 + se0 + 2] = f2tf(p11);
            }
            rs0 += __shfl_xor_sync(0xffffffffu, rs0, 1);
            rs0 += __shfl_xor_sync(0xffffffffu, rs0, 2);
            rs1 += __shfl_xor_sync(0xffffffffu, rs1, 1);
            rs1 += __shfl_xor_sync(0xffffffffu, rs1, 2);

            lst[g*2]   = lst[g*2]   * a0 + rs0;
            lst[g*2+1] = lst[g*2+1] * a1 + rs1;
            mst[g*2] = mn0; mst[g*2+1] = mn1;
            #pragma unroll
            for (int ni = 0; ni < 8; ni++) {
                oacc[g][ni][0] *= a0; oacc[g][ni][1] *= a0;
                oacc[g][ni][2] *= a1; oacc[g][ni][3] *= a1;
            }
        }
        __syncwarp();

        // O += P V : V b-frags shared across both m-groups
        #pragma unroll
        for (int s = 0; s < 8; s++) {
            uint2 p0lo = *reinterpret_cast<const uint2*>(&Pme[r * ATW + s * 8 + 2 * kq]);
            uint2 p0hi = *reinterpret_cast<const uint2*>(&Pme[(r + 8) * ATW + s * 8 + 2 * kq]);
            uint2 p1lo = *reinterpret_cast<const uint2*>(&Pme[(r + 16) * ATW + s * 8 + 2 * kq]);
            uint2 p1hi = *reinterpret_cast<const uint2*>(&Pme[(r + 24) * ATW + s * 8 + 2 * kq]);
            unsigned af0[4] = {p0lo.x, p0hi.x, p0lo.y, p0hi.y};
            unsigned af1[4] = {p1lo.x, p1hi.x, p1lo.y, p1hi.y};
            #pragma unroll
            for (int ni = 0; ni < 8; ni++) {
                uint2 vf = *reinterpret_cast<const uint2*>(
                    &Vt[(ni * 8 + r) * ATW + s * 8 + 2 * kq]);
                unsigned bf[2] = {vf.x, vf.y};
                mma8(oacc[0][ni], af0, bf);
                mma8(oacc[1][ni], af1, bf);
            }
        }
    }

    // epilogue -> g_att k-interleaved [B,T,H*dh]
    #pragma unroll
    for (int g = 0; g < 2; g++) {
        float i0 = 1.f / lst[g*2], i1 = 1.f / lst[g*2+1];
        int t0 = qb * 128 + warp * 32 + g * 16 + r;
        size_t rb0 = ((size_t)(b * SEQ + t0) * QDIM) + h * DHEAD;
        size_t rb1 = ((size_t)(b * SEQ + t0 + 8) * QDIM) + h * DHEAD;
        #pragma unroll
        for (int ni = 0; ni < 8; ni++) {
            g_att[rb0 + ni * 8 + se0]     = f2tf(oacc[g][ni][0] * i0);
            g_att[rb0 + ni * 8 + se0 + 2] = f2tf(oacc[g][ni][1] * i0);
            g_att[rb1 + ni * 8 + se0]     = f2tf(oacc[g][ni][2] * i1);
            g_att[rb1 + ni * 8 + se0 + 2] = f2tf(oacc[g][ni][3] * i1);
        }
    }
}

// ---------------------------------------------------------------------------
extern "C" void kernel_launch(void* const* d_in, const int* in_sizes, int n_in,
                              void* d_out, int out_size)
{
    const float* hidden = (const float*)d_in[0];
    const int*   amask  = (const int*)d_in[1];
    const float* Wq     = (const float*)d_in[2];
    const float* Wk     = (const float*)d_in[3];
    const float* Wv     = (const float*)d_in[4];
    const float* Wo     = (const float*)d_in[5];
    const float* bo     = (const float*)d_in[6];
    float* out          = (float*)d_out;

    cudaFuncSetAttribute(qkv_kernel,  cudaFuncAttributeMaxDynamicSharedMemorySize, GSMEM);
    cudaFuncSetAttribute(proj_kernel, cudaFuncAttributeMaxDynamicSharedMemorySize, GSMEM);
    cudaFuncSetAttribute(attn_kernel, cudaFuncAttributeMaxDynamicSharedMemorySize, ATTN_SMEM);

    cvt_hid_kernel<<<HID4 / 256, 256>>>(hidden);
    wt_kernel<<<dim3(QDIM / 32, QDIM / 32, 4), dim3(32, 8)>>>(Wq, Wk, Wv, Wo);

    dim3 gq(MROWS / 128, QDIM / 128, 3);
    qkv_kernel<<<gq, 256, GSMEM>>>();

    dim3 ga(SEQ / 128, HEADS, BATCH);
    attn_kernel<<<ga, 128, ATTN_SMEM>>>(amask);

    dim3 gp(MROWS / 128, QDIM / 128);
    proj_kernel<<<gp, 256, GSMEM>>>(bo, out);
}